// round 10
// baseline (speedup 1.0000x reference)
#include <cuda_runtime.h>
#include <cuda_bf16.h>
#include <cstdint>
#include <math.h>

// ---------------- problem constants ----------------
#define BB     64
#define D0     4096
#define D1     1024
#define D2OUT  1000
#define TT     32
#define MROWS  (BB * TT)          // 2048 GEMM rows
#define DELTA  1e-3f              // borderline-gap threshold for exact fix-up

// ---------------- device scratch (static globals; no runtime alloc) ----------------
__device__ char          g_D0a[(size_t)D0 * D0];   // w0 digit d2 (base-128 fixed point, q = w*2^24)
__device__ char          g_D0b[(size_t)D0 * D0];   // d1
__device__ char          g_D0c[(size_t)D0 * D0];   // d0
__device__ char          g_D2a[(size_t)D1 * D1];   // w2 digits (q = w*2^23); rows >= 1000 stay zero
__device__ char          g_D2b[(size_t)D1 * D1];
__device__ char          g_D2c[(size_t)D1 * D1];
__device__ char          g_A[(size_t)MROWS * D0];  // spike matrix {0,1} s8 (ld 4096 L0 / 1024 L2)
__device__ int           g_cnt0[BB * D0];
__device__ unsigned char g_N1[BB * D1];
__device__ int           g_cnt2[BB * D2OUT];
__device__ unsigned char g_flag0[BB * D0];
__device__ unsigned char g_flag2[BB * D2OUT];
__device__ uint32_t      g_ord0[BB * D0];
__device__ int           g_seg0[BB * 34];
__device__ uint32_t      g_ord2[BB * D1];
__device__ int           g_seg2[BB * 34];

// ---------------- PTX helpers (base sm_103-legal only) ----------------
__device__ __forceinline__ uint32_t smem_u32(const void* p) {
    uint32_t a;
    asm("{ .reg .u64 t; cvta.to.shared.u64 t, %1; cvt.u32.u64 %0, t; }" : "=r"(a) : "l"(p));
    return a;
}
#define CP_ASYNC16(dst, src) \
    asm volatile("cp.async.cg.shared.global [%0], [%1], 16;" :: "r"(dst), "l"(src) : "memory")
#define CP_COMMIT() asm volatile("cp.async.commit_group;" ::: "memory")
#define CP_WAIT1()  asm volatile("cp.async.wait_group 1;" ::: "memory")
#define CP_WAIT0()  asm volatile("cp.async.wait_group 0;" ::: "memory")
#define LDSM4(r0, r1, r2, r3, addr)                                              \
    asm volatile("ldmatrix.sync.aligned.m8n8.x4.shared.b16 {%0,%1,%2,%3}, [%4];" \
                 : "=r"(r0), "=r"(r1), "=r"(r2), "=r"(r3) : "r"(addr))
// int8 tensor op: m16n8k32 s8*s8 -> s32 (exact integer accumulate)
#define IMMA16832(d, a, b0_, b1_)                                                   \
    asm volatile("mma.sync.aligned.m16n8k32.row.col.s32.s8.s8.s32 "                 \
                 "{%0,%1,%2,%3},{%4,%5,%6,%7},{%8,%9},{%0,%1,%2,%3};"               \
                 : "+r"((d)[0]), "+r"((d)[1]), "+r"((d)[2]), "+r"((d)[3])           \
                 : "r"((a)[0]), "r"((a)[1]), "r"((a)[2]), "r"((a)[3]),              \
                   "r"(b0_), "r"(b1_))
#define SWZ128(off) ((off) ^ (((off) >> 3) & 0x70))

// ---------------- uniform spike pattern (reference fp32 semantics) ----------------
__device__ __forceinline__ uint32_t pattern_mask(int n) {
    if (n <= 0)  return 0u;
    if (n >= TT) return 0xFFFFFFFFu;
    float spacing = __fdiv_rn(32.0f, (float)n);
    uint32_t m = 0u;
    for (int c = 0; c < TT; c++) {
        double r = fmod((double)c, (double)spacing);
        if (r < 1.0) m |= (1u << c);
    }
    return m;
}

// ---------------- weight digitization: q = rint(w*2^s), 3 balanced base-128 int8 digits ----
// d2 = round(q/16384) (|d2| <= ~97), r in [-8192, 8191]; d1 = round(r/128) in [-64, 64];
// d0 = r - 128*d1 in [-64, 63]. w ~= (16384*d2 + 128*d1 + d0) * 2^-s, |err| <= 2^-(s+1).
template <int L>
__global__ void digit_kernel(const float* __restrict__ w) {
    size_t idx = (size_t)blockIdx.x * 256 + threadIdx.x;
    float wv = w[idx];
    int q = __float2int_rn(wv * ((L == 0) ? 16777216.0f : 8388608.0f));
    int d2 = (q + 8192) >> 14;
    int r  = q - (d2 << 14);
    int d1 = (r + 64) >> 7;
    int d0 = r - (d1 << 7);
    if (L == 0) { g_D0a[idx] = (char)d2; g_D0b[idx] = (char)d1; g_D0c[idx] = (char)d0; }
    else        { g_D2a[idx] = (char)d2; g_D2b[idx] = (char)d1; g_D2c[idx] = (char)d0; }
}

// ---------------- spike-matrix builds ({0,1} s8) ----------------
__global__ void buildA0_kernel(const float* __restrict__ x, const int* __restrict__ idx0) {
    __shared__ uint32_t spat[33];
    int tid = threadIdx.x;
    if (tid < 33) spat[tid] = pattern_mask(tid);
    __syncthreads();
    int b = blockIdx.y;
    int i = blockIdx.x * 256 + tid;
    float r = x[b * D0 + idx0[i]];
    uint32_t m = spat[__float2int_rn(r * 32.0f)];
#pragma unroll
    for (int t = 0; t < TT; t++)
        g_A[(size_t)(b * TT + t) * D0 + i] = (char)((m >> t) & 1u);
}
__global__ void buildA2_kernel(const int* __restrict__ idx2) {
    __shared__ uint32_t spat[33];
    int tid = threadIdx.x;
    if (tid < 33) spat[tid] = pattern_mask(tid);
    __syncthreads();
    int b = blockIdx.y;
    int i = blockIdx.x * 256 + tid;
    uint32_t m = spat[g_N1[b * D1 + idx2[i]]];
#pragma unroll
    for (int t = 0; t < TT; t++)
        g_A[(size_t)(b * TT + t) * D1 + i] = (char)((m >> t) & 1u);
}

// ---------------- deterministic bucket sort (spill-free; identical ord/seg to R1) ----------
template <int K>
__global__ void sort_kernel(const float* __restrict__ x, const int* __restrict__ idxg) {
    __shared__ unsigned char ns[K];
    __shared__ int cnt[128 * 33];
    __shared__ int base[34];
    int b = blockIdx.x, t = threadIdx.x;
    constexpr int CH = K / 128;

    if (K == D0) {
        for (int i = t; i < K; i += 128)
            ns[i] = (unsigned char)__float2int_rn(x[b * D0 + idxg[i]] * 32.0f);
    } else {
        for (int i = t; i < K; i += 128)
            ns[i] = g_N1[b * D1 + idxg[i]];
    }
#pragma unroll
    for (int n = 0; n < 33; n++) cnt[t * 33 + n] = 0;
    __syncthreads();
    for (int c = 0; c < CH; c++) cnt[t * 33 + ns[t * CH + c]]++;
    __syncthreads();
    if (t < 33) {
        int run = 0;
        for (int u = 0; u < 128; u++) { int v = cnt[u * 33 + t]; cnt[u * 33 + t] = run; run += v; }
        base[t] = run;
    }
    __syncthreads();
    if (t == 0) {
        int acc = 0;
        for (int n = 0; n < 33; n++) { int v = base[n]; base[n] = acc; acc += v; }
        base[33] = acc;
    }
    __syncthreads();
    uint32_t* ord = ((K == D0) ? g_ord0 : g_ord2) + (size_t)b * K;
    int* seg = ((K == D0) ? g_seg0 : g_seg2) + b * 34;
    for (int c = 0; c < CH; c++) {
        int i = t * CH + c;
        int n = ns[i];
        int pos = base[n] + cnt[t * 33 + n];
        cnt[t * 33 + n]++;
        ord[pos] = (uint32_t)i;
    }
    if (t < 34) seg[t] = base[t];
}

// ---------------- int8 digit GEMM + fused LIF scan + borderline flagging ----------------
// Block tile 128(M) x 64(N), warp tile 32x32 (8 warps). K-chunk 128 bytes (one SW128 row),
// 4 k32 steps per chunk, 3 digit matrices, s32 accumulators (exact), double-buffered cp.async.
template <int L>
__global__ void __launch_bounds__(256, 2) gemm_lif_kernel(const float* __restrict__ thr_p) {
    constexpr int KTOT = (L == 0) ? D0 : D1;
    constexpr int NC   = KTOT / 128;
    constexpr int JMAX = (L == 0) ? D0 : D2OUT;
    constexpr float SCALE = (L == 0) ? 5.9604644775390625e-8f : 1.1920928955078125e-7f; // 2^-24 / 2^-23
    constexpr uint32_t ABYTES = 16384u, BBYTES = 8192u, STAGE = ABYTES + 3u * BBYTES; // 40960

    extern __shared__ char smem[];
    uint32_t sb = smem_u32(smem);
    int tid = threadIdx.x, wid = tid >> 5, lane = tid & 31;
    int n0 = blockIdx.x * 64, m0 = blockIdx.y * 128;
    int wm = wid >> 1, wn = wid & 1;          // warp grid 4(m) x 2(n)
    const int mW = wm * 32, nW = wn * 32;

    const char* Dg[3];
    if (L == 0) { Dg[0] = g_D0a; Dg[1] = g_D0b; Dg[2] = g_D0c; }
    else        { Dg[0] = g_D2a; Dg[1] = g_D2b; Dg[2] = g_D2c; }

    auto load_stage = [&](int stage, int kc) {
        uint32_t st = sb + (uint32_t)stage * STAGE;
        int k0 = kc * 128;
#pragma unroll
        for (int u = 0; u < 4; u++) {          // A: 128 rows x 128 B
            int slot = u * 256 + tid, r = slot >> 3, kk = slot & 7;
            const char* gp = g_A + (size_t)(m0 + r) * KTOT + k0 + kk * 16;
            CP_ASYNC16(st + SWZ128((uint32_t)(r * 128 + kk * 16)), gp);
        }
#pragma unroll
        for (int d = 0; d < 3; d++) {          // each digit: 64 rows x 128 B
            uint32_t bb = st + ABYTES + (uint32_t)d * BBYTES;
#pragma unroll
            for (int u = 0; u < 2; u++) {
                int slot = u * 256 + tid, r = slot >> 3, kk = slot & 7;
                const char* gp = Dg[d] + (size_t)(n0 + r) * KTOT + k0 + kk * 16;
                CP_ASYNC16(bb + SWZ128((uint32_t)(r * 128 + kk * 16)), gp);
            }
        }
        CP_COMMIT();
    };

    int S[3][2][4][4];                          // [digit][mf][n8][reg] s32, exact
#pragma unroll
    for (int d = 0; d < 3; d++)
#pragma unroll
        for (int mf = 0; mf < 2; mf++)
#pragma unroll
            for (int nf = 0; nf < 4; nf++)
#pragma unroll
                for (int c = 0; c < 4; c++) S[d][mf][nf][c] = 0;

    int q = lane >> 3, w8 = lane & 7;

    load_stage(0, 0);
#pragma unroll 1
    for (int c = 0; c < NC; c++) {
        if (c + 1 < NC) { load_stage((c + 1) & 1, c + 1); CP_WAIT1(); }
        else            { CP_WAIT0(); }
        __syncthreads();

        uint32_t st = sb + (uint32_t)(c & 1) * STAGE;
#pragma unroll
        for (int ks = 0; ks < 4; ks++) {        // k32 steps (32 bytes each)
            uint32_t af[2][4];
#pragma unroll
            for (int mf = 0; mf < 2; mf++) {
                int row = mW + mf * 16 + w8 + (q & 1) * 8;
                int colb = ks * 32 + (q >> 1) * 16;
                LDSM4(af[mf][0], af[mf][1], af[mf][2], af[mf][3],
                      st + SWZ128((uint32_t)(row * 128 + colb)));
            }
#pragma unroll
            for (int d = 0; d < 3; d++) {
                uint32_t bb = st + ABYTES + (uint32_t)d * BBYTES;
#pragma unroll
                for (int h = 0; h < 2; h++) {   // two n16 halves of the 32-wide warp n-tile
                    uint32_t b0, b1, b2, b3;
                    int row = nW + h * 16 + w8 + (q >> 1) * 8;
                    int colb = ks * 32 + (q & 1) * 16;
                    LDSM4(b0, b1, b2, b3, bb + SWZ128((uint32_t)(row * 128 + colb)));
                    IMMA16832(S[d][0][2 * h + 0], af[0], b0, b1);
                    IMMA16832(S[d][0][2 * h + 1], af[0], b2, b3);
                    IMMA16832(S[d][1][2 * h + 0], af[1], b0, b1);
                    IMMA16832(S[d][1][2 * h + 1], af[1], b2, b3);
                }
            }
        }
        __syncthreads();
    }

    // ---- epilogue: combine digits, transpose through padded smem, LIF scan + gap flag ----
    float* ct = (float*)smem;                   // [128][65] fp32 = 33280 B
#pragma unroll
    for (int mf = 0; mf < 2; mf++)
#pragma unroll
        for (int nf = 0; nf < 4; nf++) {
            int row = mW + mf * 16 + (lane >> 2);
            int col = nW + nf * 8 + 2 * (lane & 3);
#pragma unroll
            for (int cc = 0; cc < 4; cc++) {
                float v = fmaf(16384.0f, (float)S[0][mf][nf][cc],
                               fmaf(128.0f, (float)S[1][mf][nf][cc],
                                    (float)S[2][mf][nf][cc])) * SCALE;
                int rr = row + ((cc >> 1) ? 8 : 0);
                int co = col + (cc & 1);
                ct[rr * 65 + co] = v;
            }
        }
    __syncthreads();

    float thr = *thr_p;
    int* cnt_out = (L == 0) ? g_cnt0 : g_cnt2;
    unsigned char* flag_out = (L == 0) ? g_flag0 : g_flag2;
    {
        int bl = tid >> 6, j = tid & 63;        // 4 batches x 64 j = 256 pairs
        float memb = 0.f, ming = 1e30f;
        int cnt = 0;
#pragma unroll
        for (int t = 0; t < TT; t++) {
            memb += ct[(bl * 32 + t) * 65 + j];
            float g = fabsf(memb - thr);
            if (g < ming) ming = g;
            if (memb > thr) { memb -= thr; cnt++; }
        }
        int bglob = blockIdx.y * 4 + bl;
        int jglob = n0 + j;
        if (jglob < JMAX) {
            cnt_out[(size_t)bglob * JMAX + jglob] = cnt;
            flag_out[(size_t)bglob * JMAX + jglob] = (ming < DELTA) ? 1 : 0;
        }
    }
}

// ---------------- exact fix-up: replicate R1's bit-exact scalar path for flagged entries ----
template <int L>
__global__ void fixup_kernel(const float* __restrict__ w, const float* __restrict__ thr_p) {
    constexpr int K    = (L == 0) ? D0 : D1;
    constexpr int JMAX = (L == 0) ? D0 : D2OUT;
    __shared__ uint32_t spat[33];
    int tid = threadIdx.x;
    if (tid < 33) spat[tid] = pattern_mask(tid);
    __syncthreads();

    int b = blockIdx.y;
    int j = blockIdx.x * 256 + tid;
    if (j >= JMAX) return;
    const unsigned char* flag = (L == 0) ? g_flag0 : g_flag2;
    if (!flag[(size_t)b * JMAX + j]) return;

    const uint32_t* po = ((L == 0) ? g_ord0 : g_ord2) + b * K;
    const int*      sg = ((L == 0) ? g_seg0 : g_seg2) + b * 34;
    const float* wrow = w + (size_t)j * K;

    float I[TT];
#pragma unroll
    for (int t = 0; t < TT; t++) I[t] = 0.f;

#pragma unroll 1
    for (int n = 1; n < 33; n++) {
        int s = sg[n], e = sg[n + 1];
        if (s >= e) continue;
        float a0 = 0.f, a1 = 0.f, a2 = 0.f, a3 = 0.f;
        int k = s;
        float p0 = 0.f, p1 = 0.f, p2 = 0.f, p3 = 0.f;
        if (k + 4 <= e) {
            p0 = wrow[po[k]]; p1 = wrow[po[k + 1]];
            p2 = wrow[po[k + 2]]; p3 = wrow[po[k + 3]];
        }
#pragma unroll 1
        for (; k + 4 <= e; ) {
            float c0 = p0, c1 = p1, c2 = p2, c3 = p3;
            int kn = k + 4;
            if (kn + 4 <= e) {
                p0 = wrow[po[kn]]; p1 = wrow[po[kn + 1]];
                p2 = wrow[po[kn + 2]]; p3 = wrow[po[kn + 3]];
            }
            a0 += c0; a1 += c1; a2 += c2; a3 += c3;   // R1 add order
            k = kn;
        }
        for (; k < e; k++) a0 += wrow[po[k]];
        float acc = (a0 + a1) + (a2 + a3);
        uint32_t m = spat[n];
#pragma unroll
        for (int t = 0; t < TT; t++)
            if ((m >> t) & 1u) I[t] += acc;
    }

    float thr = *thr_p;
    float memb = 0.f;
    int cnt = 0;
#pragma unroll
    for (int t = 0; t < TT; t++) {
        memb += I[t];
        if (memb > thr) { memb -= thr; cnt++; }
    }
    if (L == 0) g_cnt0[b * D0 + j] = cnt; else g_cnt2[b * D2OUT + j] = cnt;
}

// ---------------- pooling + layer-1 re-encoding (exact integer/pow2 arithmetic) ----------------
__global__ void mid_kernel(const int* __restrict__ idx1) {
    int b = blockIdx.x, p = threadIdx.x;
    int ch = p >> 4, oh = (p >> 2) & 3, ow = p & 3;
    int c = 0;
#pragma unroll
    for (int dh = 0; dh < 2; dh++)
#pragma unroll
        for (int dw = 0; dw < 2; dw++) {
            int k = ch * 64 + (2 * oh + dh) * 8 + (2 * ow + dw);
            c += g_cnt0[b * D0 + idx1[k]];
        }
    g_N1[b * D1 + p] = (unsigned char)__float2int_rn((float)c * 0.25f);
}

// ---------------- output gather ----------------
__global__ void out_kernel(const int* __restrict__ idx_out, float* __restrict__ out) {
    int b = blockIdx.x, j = threadIdx.x;
    if (j < D2OUT) out[b * D2OUT + j] = (float)g_cnt2[b * D2OUT + idx_out[j]];
}

// ---------------- launch ----------------
extern "C" void kernel_launch(void* const* d_in, const int* in_sizes, int n_in,
                              void* d_out, int out_size) {
    (void)in_sizes; (void)n_in; (void)out_size;
    const float* x       = (const float*)d_in[0];
    const float* w0      = (const float*)d_in[1];
    const float* t0      = (const float*)d_in[2];
    const float* w2      = (const float*)d_in[3];
    const float* t2      = (const float*)d_in[4];
    const int*   idx0    = (const int*)d_in[5];
    const int*   idx1    = (const int*)d_in[6];
    const int*   idx2    = (const int*)d_in[7];
    const int*   idx_out = (const int*)d_in[8];
    float* out = (float*)d_out;

    const int SMEM_TOTAL = 2 * 40960;   // 80 KB -> 2 CTAs/SM
    cudaFuncSetAttribute(gemm_lif_kernel<0>, cudaFuncAttributeMaxDynamicSharedMemorySize, SMEM_TOTAL);
    cudaFuncSetAttribute(gemm_lif_kernel<1>, cudaFuncAttributeMaxDynamicSharedMemorySize, SMEM_TOTAL);

    digit_kernel<0><<<(int)(((size_t)D0 * D0) / 256), 256>>>(w0);
    digit_kernel<1><<<(D2OUT * D1) / 256, 256>>>(w2);

    buildA0_kernel<<<dim3(D0 / 256, BB), 256>>>(x, idx0);
    sort_kernel<D0><<<BB, 128>>>(x, idx0);
    gemm_lif_kernel<0><<<dim3(D0 / 64, MROWS / 128), 256, SMEM_TOTAL>>>(t0);
    fixup_kernel<0><<<dim3(D0 / 256, BB), 256>>>(w0, t0);

    mid_kernel<<<BB, D1>>>(idx1);
    buildA2_kernel<<<dim3(D1 / 256, BB), 256>>>(idx2);
    sort_kernel<D1><<<BB, 128>>>(x, idx2);
    gemm_lif_kernel<1><<<dim3(D1 / 64, MROWS / 128), 256, SMEM_TOTAL>>>(t2);
    fixup_kernel<1><<<dim3(4, BB), 256>>>(w2, t2);

    out_kernel<<<BB, 1024>>>(idx_out, out);
}

// round 12
// speedup vs baseline: 1.7105x; 1.7105x over previous
#include <cuda_runtime.h>
#include <cuda_bf16.h>
#include <cstdint>
#include <math.h>

// ---------------- problem constants ----------------
#define BB     64
#define D0     4096
#define D1     1024
#define D2OUT  1000
#define TT     32
#define MROWS  (BB * TT)          // 2048 GEMM rows
#define DELTA  1e-3f              // borderline-gap threshold for exact fix-up

// ---------------- device scratch (static globals; no runtime alloc) ----------------
__device__ __nv_bfloat16 g_Bh[(size_t)D0 * D0];    // w0 hi split, row-major [j][i]
__device__ __nv_bfloat16 g_Bm[(size_t)D0 * D0];    // w0 mid split
__device__ float         g_Wt0[(size_t)D0 * D0];   // w0 transposed: Wt0[i*D0 + j] = w0[j][i]
__device__ __nv_bfloat16 g_B2h[(size_t)D1 * D1];   // w2 splits; rows >= 1000 stay zero
__device__ __nv_bfloat16 g_B2m[(size_t)D1 * D1];
__device__ float         g_Wt2[(size_t)D1 * D1];   // w2 transposed, stride 1024 (j < 1000 valid)
__device__ __nv_bfloat16 g_A[(size_t)MROWS * D0];  // spike matrix (ld 4096 L0 / 1024 L2)
__device__ int           g_cnt0[BB * D0];
__device__ unsigned char g_N1[BB * D1];
__device__ int           g_cnt2[BB * D2OUT];
__device__ unsigned char g_flag0[BB * D0];
__device__ unsigned char g_flag2[BB * D2OUT];
__device__ uint32_t      g_ord0[BB * D0];
__device__ int           g_seg0[BB * 34];
__device__ uint32_t      g_ord2[BB * D1];
__device__ int           g_seg2[BB * 34];

// ---------------- PTX helpers (base sm_103-legal only) ----------------
__device__ __forceinline__ uint32_t smem_u32(const void* p) {
    uint32_t a;
    asm("{ .reg .u64 t; cvta.to.shared.u64 t, %1; cvt.u32.u64 %0, t; }" : "=r"(a) : "l"(p));
    return a;
}
#define CP_ASYNC16(dst, src) \
    asm volatile("cp.async.cg.shared.global [%0], [%1], 16;" :: "r"(dst), "l"(src) : "memory")
#define CP_COMMIT() asm volatile("cp.async.commit_group;" ::: "memory")
#define CP_WAIT2()  asm volatile("cp.async.wait_group 2;" ::: "memory")
#define CP_WAIT1()  asm volatile("cp.async.wait_group 1;" ::: "memory")
#define CP_WAIT0()  asm volatile("cp.async.wait_group 0;" ::: "memory")
#define LDSM4(r0, r1, r2, r3, addr)                                              \
    asm volatile("ldmatrix.sync.aligned.m8n8.x4.shared.b16 {%0,%1,%2,%3}, [%4];" \
                 : "=r"(r0), "=r"(r1), "=r"(r2), "=r"(r3) : "r"(addr))
#define MMA16816(d, a, b0, b1)                                                      \
    asm volatile("mma.sync.aligned.m16n8k16.row.col.f32.bf16.bf16.f32 "             \
                 "{%0,%1,%2,%3},{%4,%5,%6,%7},{%8,%9},{%0,%1,%2,%3};"               \
                 : "+f"((d)[0]), "+f"((d)[1]), "+f"((d)[2]), "+f"((d)[3])           \
                 : "r"((a)[0]), "r"((a)[1]), "r"((a)[2]), "r"((a)[3]),              \
                   "r"(b0), "r"(b1))
#define SWZ128(off) ((off) ^ (((off) >> 3) & 0x70))

// ---------------- uniform spike pattern (reference fp32 semantics) ----------------
__device__ __forceinline__ uint32_t pattern_mask(int n) {
    if (n <= 0)  return 0u;
    if (n >= TT) return 0xFFFFFFFFu;
    float spacing = __fdiv_rn(32.0f, (float)n);
    uint32_t m = 0u;
    for (int c = 0; c < TT; c++) {
        double r = fmod((double)c, (double)spacing);
        if (r < 1.0) m |= (1u << c);
    }
    return m;
}

// ---------------- fused split (hi+mid bf16) + transpose ----------------
__global__ void prep0_kernel(const float* __restrict__ w) {
    __shared__ float tile[32][33];
    int c0 = blockIdx.x * 32, r0 = blockIdx.y * 32;
    int tx = threadIdx.x, ty = threadIdx.y;
    int cx = c0 + tx;
#pragma unroll
    for (int dy = 0; dy < 32; dy += 8) {
        int r = r0 + ty + dy;
        float v = w[(size_t)r * D0 + cx];
        tile[ty + dy][tx] = v;
        __nv_bfloat16 h = __float2bfloat16(v);
        g_Bh[(size_t)r * D0 + cx] = h;
        g_Bm[(size_t)r * D0 + cx] = __float2bfloat16(v - __bfloat162float(h));
    }
    __syncthreads();
    int rx = r0 + tx;
#pragma unroll
    for (int dy = 0; dy < 32; dy += 8) {
        int c = c0 + ty + dy;
        g_Wt0[(size_t)c * D0 + rx] = tile[tx][ty + dy];
    }
}
__global__ void prep2_kernel(const float* __restrict__ w) {   // rows=1000, cols=1024
    __shared__ float tile[32][33];
    int c0 = blockIdx.x * 32, r0 = blockIdx.y * 32;
    int tx = threadIdx.x, ty = threadIdx.y;
    int cx = c0 + tx;
#pragma unroll
    for (int dy = 0; dy < 32; dy += 8) {
        int r = r0 + ty + dy;
        float v = (r < D2OUT) ? w[(size_t)r * D1 + cx] : 0.f;
        tile[ty + dy][tx] = v;
        if (r < D2OUT) {
            __nv_bfloat16 h = __float2bfloat16(v);
            g_B2h[(size_t)r * D1 + cx] = h;
            g_B2m[(size_t)r * D1 + cx] = __float2bfloat16(v - __bfloat162float(h));
        }
    }
    __syncthreads();
    int rx = r0 + tx;
#pragma unroll
    for (int dy = 0; dy < 32; dy += 8) {
        int c = c0 + ty + dy;
        g_Wt2[(size_t)c * D1 + rx] = tile[tx][ty + dy];   // rx may be >= 1000: padding, unused
    }
}

// ---------------- spike-matrix builds (bf16 {0,1}) ----------------
__global__ void buildA0_kernel(const float* __restrict__ x, const int* __restrict__ idx0) {
    __shared__ uint32_t spat[33];
    int tid = threadIdx.x;
    if (tid < 33) spat[tid] = pattern_mask(tid);
    __syncthreads();
    int b = blockIdx.y;
    int i = blockIdx.x * 256 + tid;
    float r = x[b * D0 + idx0[i]];
    uint32_t m = spat[__float2int_rn(r * 32.0f)];
    unsigned short* A = (unsigned short*)g_A;
#pragma unroll
    for (int t = 0; t < TT; t++)
        A[(size_t)(b * TT + t) * D0 + i] = ((m >> t) & 1u) ? (unsigned short)0x3F80 : (unsigned short)0;
}
__global__ void buildA2_kernel(const int* __restrict__ idx2) {
    __shared__ uint32_t spat[33];
    int tid = threadIdx.x;
    if (tid < 33) spat[tid] = pattern_mask(tid);
    __syncthreads();
    int b = blockIdx.y;
    int i = blockIdx.x * 256 + tid;
    uint32_t m = spat[g_N1[b * D1 + idx2[i]]];
    unsigned short* A = (unsigned short*)g_A;
#pragma unroll
    for (int t = 0; t < TT; t++)
        A[(size_t)(b * TT + t) * D1 + i] = ((m >> t) & 1u) ? (unsigned short)0x3F80 : (unsigned short)0;
}

// ---------------- deterministic bucket sort (spill-free; identical ord/seg to R1) ----------
template <int K>
__global__ void sort_kernel(const float* __restrict__ x, const int* __restrict__ idxg) {
    __shared__ unsigned char ns[K];
    __shared__ int cnt[128 * 33];
    __shared__ int base[34];
    int b = blockIdx.x, t = threadIdx.x;
    constexpr int CH = K / 128;

    if (K == D0) {
        for (int i = t; i < K; i += 128)
            ns[i] = (unsigned char)__float2int_rn(x[b * D0 + idxg[i]] * 32.0f);
    } else {
        for (int i = t; i < K; i += 128)
            ns[i] = g_N1[b * D1 + idxg[i]];
    }
#pragma unroll
    for (int n = 0; n < 33; n++) cnt[t * 33 + n] = 0;
    __syncthreads();
    for (int c = 0; c < CH; c++) cnt[t * 33 + ns[t * CH + c]]++;
    __syncthreads();
    if (t < 33) {
        int run = 0;
        for (int u = 0; u < 128; u++) { int v = cnt[u * 33 + t]; cnt[u * 33 + t] = run; run += v; }
        base[t] = run;
    }
    __syncthreads();
    if (t == 0) {
        int acc = 0;
        for (int n = 0; n < 33; n++) { int v = base[n]; base[n] = acc; acc += v; }
        base[33] = acc;
    }
    __syncthreads();
    uint32_t* ord = ((K == D0) ? g_ord0 : g_ord2) + (size_t)b * K;
    int* seg = ((K == D0) ? g_seg0 : g_seg2) + b * 34;
    for (int c = 0; c < CH; c++) {
        int i = t * CH + c;
        int n = ns[i];
        int pos = base[n] + cnt[t * 33 + n];
        cnt[t * 33 + n]++;
        ord[pos] = (uint32_t)i;
    }
    if (t < 34) seg[t] = base[t];
}

// ---------------- GEMM (2 bf16 splits) + fused LIF scan + borderline flagging ----------
// Block tile 128x128, warp tile 32x64 (8 warps), K-chunk 64, 3-stage cp.async pipeline,
// 1 CTA/SM with full register budget (R8 evidence: best TF/s regime on the legacy pipe).
template <int L>
__global__ void __launch_bounds__(256, 1) gemm_lif_kernel(const float* __restrict__ thr_p) {
    constexpr int KTOT = (L == 0) ? D0 : D1;
    constexpr int NC   = KTOT / 64;
    constexpr int JMAX = (L == 0) ? D0 : D2OUT;
    constexpr uint32_t STAGE = 49152u;   // A(16K) + Bh(16K) + Bm(16K)

    extern __shared__ char smem[];
    uint32_t sb = smem_u32(smem);
    int tid = threadIdx.x, wid = tid >> 5, lane = tid & 31;
    int n0 = blockIdx.x * 128, m0 = blockIdx.y * 128;
    int wm = wid >> 1, wn = wid & 1;
    const int mW = wm * 32, nW = wn * 64;

    const __nv_bfloat16* Bs[2];
    if (L == 0) { Bs[0] = g_Bh; Bs[1] = g_Bm; }
    else        { Bs[0] = g_B2h; Bs[1] = g_B2m; }

    auto load_stage = [&](int stage, int kc) {
        uint32_t st = sb + (uint32_t)stage * STAGE;
        int k0 = kc * 64;
#pragma unroll
        for (int u = 0; u < 4; u++) {
            int slot = u * 256 + tid, r = slot >> 3, kk = slot & 7;
            const __nv_bfloat16* gp = g_A + (size_t)(m0 + r) * KTOT + k0 + kk * 8;
            CP_ASYNC16(st + SWZ128((uint32_t)(r * 128 + kk * 16)), gp);
        }
#pragma unroll
        for (int s = 0; s < 2; s++) {
            uint32_t bb = st + 16384u * (1 + s);
#pragma unroll
            for (int u = 0; u < 4; u++) {
                int slot = u * 256 + tid, r = slot >> 3, kk = slot & 7;
                const __nv_bfloat16* gp = Bs[s] + (size_t)(n0 + r) * KTOT + k0 + kk * 8;
                CP_ASYNC16(bb + SWZ128((uint32_t)(r * 128 + kk * 16)), gp);
            }
        }
        CP_COMMIT();
    };

    float acc[2][8][4];
#pragma unroll
    for (int a = 0; a < 2; a++)
#pragma unroll
        for (int b = 0; b < 8; b++)
#pragma unroll
            for (int c = 0; c < 4; c++) acc[a][b][c] = 0.f;

    int q = lane >> 3, w8 = lane & 7;

    load_stage(0, 0);
    load_stage(1, 1);
#pragma unroll 1
    for (int c = 0; c < NC; c++) {
        if (c + 2 < NC) { load_stage((c + 2) % 3, c + 2); CP_WAIT2(); }
        else if (c + 1 < NC) { CP_WAIT1(); }
        else { CP_WAIT0(); }
        __syncthreads();

        uint32_t st = sb + (uint32_t)(c % 3) * STAGE;
#pragma unroll
        for (int ks = 0; ks < 4; ks++) {
            uint32_t af[2][4];
#pragma unroll
            for (int mf = 0; mf < 2; mf++) {
                int row = mW + mf * 16 + w8 + (q & 1) * 8;
                int colb = ks * 32 + (q >> 1) * 16;
                LDSM4(af[mf][0], af[mf][1], af[mf][2], af[mf][3],
                      st + SWZ128((uint32_t)(row * 128 + colb)));
            }
#pragma unroll
            for (int s = 0; s < 2; s++) {
                uint32_t bbase = st + 16384u * (1 + s);
#pragma unroll
                for (int nfp = 0; nfp < 4; nfp++) {
                    uint32_t b0, b1, b2, b3;
                    int row = nW + nfp * 16 + w8 + (q >> 1) * 8;
                    int colb = ks * 32 + (q & 1) * 16;
                    LDSM4(b0, b1, b2, b3, bbase + SWZ128((uint32_t)(row * 128 + colb)));
                    MMA16816(acc[0][2 * nfp + 0], af[0], b0, b1);
                    MMA16816(acc[0][2 * nfp + 1], af[0], b2, b3);
                    MMA16816(acc[1][2 * nfp + 0], af[1], b0, b1);
                    MMA16816(acc[1][2 * nfp + 1], af[1], b2, b3);
                }
            }
        }
        __syncthreads();
    }

    // ---- epilogue: transpose C through padded smem tile, LIF scan + gap flag ----
    float* ct = (float*)smem;                         // [128][129] fp32 (66 KB < 144 KB)
#pragma unroll
    for (int mf = 0; mf < 2; mf++)
#pragma unroll
        for (int nf = 0; nf < 8; nf++) {
            int row = mW + mf * 16 + (lane >> 2);
            int col = nW + nf * 8 + 2 * (lane & 3);
            ct[row * 129 + col]           = acc[mf][nf][0];
            ct[row * 129 + col + 1]       = acc[mf][nf][1];
            ct[(row + 8) * 129 + col]     = acc[mf][nf][2];
            ct[(row + 8) * 129 + col + 1] = acc[mf][nf][3];
        }
    __syncthreads();

    float thr = *thr_p;
    int* cnt_out = (L == 0) ? g_cnt0 : g_cnt2;
    unsigned char* flag_out = (L == 0) ? g_flag0 : g_flag2;
#pragma unroll
    for (int pp = 0; pp < 2; pp++) {
        int p = pp * 256 + tid;
        int bl = p >> 7, j = p & 127;
        float memb = 0.f, ming = 1e30f;
        int cnt = 0;
#pragma unroll
        for (int t = 0; t < TT; t++) {
            memb += ct[(bl * 32 + t) * 129 + j];
            float g = fabsf(memb - thr);
            if (g < ming) ming = g;
            if (memb > thr) { memb -= thr; cnt++; }
        }
        int bglob = blockIdx.y * 4 + bl;
        int jglob = n0 + j;
        if (jglob < JMAX) {
            cnt_out[(size_t)bglob * JMAX + jglob] = cnt;
            flag_out[(size_t)bglob * JMAX + jglob] = (ming < DELTA) ? 1 : 0;
        }
    }
}

// ---------------- exact fix-up (R1 value order, COALESCED via transposed weights) --------
// Reads Wt[po[k]*ldw + j]: warp lanes j consecutive -> one 128B line per load.
// Value sequence identical to R1's bit-exact path (rel_err 0.0 three times).
template <int L>
__global__ void fixup_kernel(const float* __restrict__ thr_p) {
    constexpr int K    = (L == 0) ? D0 : D1;
    constexpr int LDW  = (L == 0) ? D0 : D1;
    constexpr int JMAX = (L == 0) ? D0 : D2OUT;
    __shared__ uint32_t spat[33];
    int tid = threadIdx.x;
    if (tid < 33) spat[tid] = pattern_mask(tid);
    __syncthreads();

    int b = blockIdx.y;
    int j = blockIdx.x * 256 + tid;
    if (j >= JMAX) return;
    const unsigned char* flag = (L == 0) ? g_flag0 : g_flag2;
    if (!flag[(size_t)b * JMAX + j]) return;

    const uint32_t* po = ((L == 0) ? g_ord0 : g_ord2) + b * K;
    const int*      sg = ((L == 0) ? g_seg0 : g_seg2) + b * 34;
    const float* wt = ((L == 0) ? g_Wt0 : g_Wt2) + j;

    float I[TT];
#pragma unroll
    for (int t = 0; t < TT; t++) I[t] = 0.f;

#pragma unroll 1
    for (int n = 1; n < 33; n++) {
        int s = sg[n], e = sg[n + 1];
        if (s >= e) continue;
        float a0 = 0.f, a1 = 0.f, a2 = 0.f, a3 = 0.f;
        int k = s;
        float p0 = 0.f, p1 = 0.f, p2 = 0.f, p3 = 0.f;
        if (k + 4 <= e) {
            p0 = wt[(size_t)po[k] * LDW];     p1 = wt[(size_t)po[k + 1] * LDW];
            p2 = wt[(size_t)po[k + 2] * LDW]; p3 = wt[(size_t)po[k + 3] * LDW];
        }
#pragma unroll 1
        for (; k + 4 <= e; ) {
            float c0 = p0, c1 = p1, c2 = p2, c3 = p3;
            int kn = k + 4;
            if (kn + 4 <= e) {
                p0 = wt[(size_t)po[kn] * LDW];     p1 = wt[(size_t)po[kn + 1] * LDW];
                p2 = wt[(size_t)po[kn + 2] * LDW]; p3 = wt[(size_t)po[kn + 3] * LDW];
            }
            a0 += c0; a1 += c1; a2 += c2; a3 += c3;   // R1 add order
            k = kn;
        }
        for (; k < e; k++) a0 += wt[(size_t)po[k] * LDW];
        float acc = (a0 + a1) + (a2 + a3);
        uint32_t m = spat[n];
#pragma unroll
        for (int t = 0; t < TT; t++)
            if ((m >> t) & 1u) I[t] += acc;
    }

    float thr = *thr_p;
    float memb = 0.f;
    int cnt = 0;
#pragma unroll
    for (int t = 0; t < TT; t++) {
        memb += I[t];
        if (memb > thr) { memb -= thr; cnt++; }
    }
    if (L == 0) g_cnt0[b * D0 + j] = cnt; else g_cnt2[b * D2OUT + j] = cnt;
}

// ---------------- pooling + layer-1 re-encoding (exact integer/pow2 arithmetic) ----------------
__global__ void mid_kernel(const int* __restrict__ idx1) {
    int b = blockIdx.x, p = threadIdx.x;
    int ch = p >> 4, oh = (p >> 2) & 3, ow = p & 3;
    int c = 0;
#pragma unroll
    for (int dh = 0; dh < 2; dh++)
#pragma unroll
        for (int dw = 0; dw < 2; dw++) {
            int k = ch * 64 + (2 * oh + dh) * 8 + (2 * ow + dw);
            c += g_cnt0[b * D0 + idx1[k]];
        }
    g_N1[b * D1 + p] = (unsigned char)__float2int_rn((float)c * 0.25f);
}

// ---------------- output gather ----------------
__global__ void out_kernel(const int* __restrict__ idx_out, float* __restrict__ out) {
    int b = blockIdx.x, j = threadIdx.x;
    if (j < D2OUT) out[b * D2OUT + j] = (float)g_cnt2[b * D2OUT + idx_out[j]];
}

// ---------------- launch ----------------
extern "C" void kernel_launch(void* const* d_in, const int* in_sizes, int n_in,
                              void* d_out, int out_size) {
    (void)in_sizes; (void)n_in; (void)out_size;
    const float* x       = (const float*)d_in[0];
    const float* w0      = (const float*)d_in[1];
    const float* t0      = (const float*)d_in[2];
    const float* w2      = (const float*)d_in[3];
    const float* t2      = (const float*)d_in[4];
    const int*   idx0    = (const int*)d_in[5];
    const int*   idx1    = (const int*)d_in[6];
    const int*   idx2    = (const int*)d_in[7];
    const int*   idx_out = (const int*)d_in[8];
    float* out = (float*)d_out;

    const int SMEM_TOTAL = 3 * 49152;   // 144 KB, 3-stage pipeline, 1 CTA/SM
    cudaFuncSetAttribute(gemm_lif_kernel<0>, cudaFuncAttributeMaxDynamicSharedMemorySize, SMEM_TOTAL);
    cudaFuncSetAttribute(gemm_lif_kernel<1>, cudaFuncAttributeMaxDynamicSharedMemorySize, SMEM_TOTAL);

    dim3 tb(32, 8);
    prep0_kernel<<<dim3(D0 / 32, D0 / 32), tb>>>(w0);
    prep2_kernel<<<dim3(D1 / 32, D1 / 32), tb>>>(w2);

    buildA0_kernel<<<dim3(D0 / 256, BB), 256>>>(x, idx0);
    sort_kernel<D0><<<BB, 128>>>(x, idx0);
    gemm_lif_kernel<0><<<dim3(D0 / 128, MROWS / 128), 256, SMEM_TOTAL>>>(t0);
    fixup_kernel<0><<<dim3(D0 / 256, BB), 256>>>(t0);

    mid_kernel<<<BB, D1>>>(idx1);
    buildA2_kernel<<<dim3(D1 / 256, BB), 256>>>(idx2);
    sort_kernel<D1><<<BB, 128>>>(x, idx2);
    gemm_lif_kernel<1><<<dim3(D1 / 128, MROWS / 128), 256, SMEM_TOTAL>>>(t2);
    fixup_kernel<1><<<dim3(4, BB), 256>>>(t2);

    out_kernel<<<BB, 1024>>>(idx_out, out);
}